// round 5
// baseline (speedup 1.0000x reference)
#include <cuda_runtime.h>
#include <cuda_bf16.h>
#include <cstdint>

// QSRGAN: x [256,256,5] f32, q_params [4,30] f32 -> out [4,512,512,16] f32.
//
// Single fused kernel:
//  Phase A (warps 0-3 of each block): evolve the 32 basis columns through the
//    6-layer RY+CZ circuit for all 4 generators; emit W rows 0..15 directly as
//    tf32 hi/lo mma B-fragments into shared memory (redundant per block, but
//    removes the separate precompute kernel + launch gap).
//  Phase B (all threads): bilinear upsample 5 angles, poly sincos, build the
//    rank-1 product state (32 amps), stage to smem for fragment transposition.
//  Phase C: per warp = 32 pixels, two m16 tiles; per tile load A hi/lo tf32
//    fragments once, then per generator accumulate the [16x32]x[32x16] product
//    with mma.sync.m16n8k8.tf32 (3-term split = fp32 accuracy), epilogue:
//    square, quad-shuffle max, normalize, store.
//  (sum-normalization cancels: p/sum/max(p/sum) = p/max(p))
//
// B fragment smem layout (float units), for g in 0..3, kt in 0..3, lane:
//   base = ((g*4+kt)*32 + lane)*8
//   [base+0,1] = hi b-regs (r=0,1) of n-tile 0 (gen cols 0..7)
//   [base+2,3] = lo b-regs of n-tile 0
//   [base+4..7] = same for n-tile 1 (gen cols 8..15)
// -> one LDS.128 per (g,kt,n-tile) fetches (hi,lo) together.

#define DIM 32
#define KEEPN 16
#define NGEN 4
#define IW 256
#define NPIX (512*512)
#define SSTRIDE 36          // state staging row stride (floats), conflict-free

__device__ __forceinline__ uint32_t f2tf32(float x) {
    uint32_t u;
    asm("cvt.rna.tf32.f32 %0, %1;" : "=r"(u) : "f"(x));
    return u;
}

#define MMA_TF32(C, A, B0, B1)                                                 \
    asm volatile("mma.sync.aligned.m16n8k8.row.col.f32.tf32.tf32.f32 "         \
                 "{%0,%1,%2,%3}, {%4,%5,%6,%7}, {%8,%9}, {%0,%1,%2,%3};"       \
                 : "+f"((C)[0]), "+f"((C)[1]), "+f"((C)[2]), "+f"((C)[3])      \
                 : "r"((A)[0]), "r"((A)[1]), "r"((A)[2]), "r"((A)[3]),         \
                   "r"(B0), "r"(B1))

__global__ void __launch_bounds__(256, 3) qsrgan_fused_kernel(
    const float* __restrict__ x, const float* __restrict__ qp,
    float* __restrict__ out)
{
    extern __shared__ float smem[];
    float* shB = smem;                 // 4096 floats: B fragments
    float* shS = smem + 4096;          // 8 warps * 32 rows * SSTRIDE floats

    const int tid  = threadIdx.x;
    const int lane = tid & 31;
    const int warp = tid >> 5;

    // ---------------- Phase A: W fragments (threads 0..127) ----------------
    if (tid < 128) {
        const int g = tid >> 5;        // generator
        const int j = tid & 31;        // basis column (= GEMM k index)

        float st[DIM];
#pragma unroll
        for (int i = 0; i < DIM; i++) st[i] = (i == j) ? 1.0f : 0.0f;

#pragma unroll
        for (int d = 0; d < 6; d++) {
#pragma unroll
            for (int q = 0; q < 5; q++) {
                float th = 0.5f * qp[g * 30 + d * 5 + q];
                float s, c;
                sincosf(th, &s, &c);
                const int r = 1 << (4 - q);
#pragma unroll
                for (int i = 0; i < DIM; i++) {
                    if ((i & r) == 0) {
                        float a0 = st[i];
                        float a1 = st[i | r];
                        st[i]     = c * a0 - s * a1;
                        st[i | r] = s * a0 + c * a1;
                    }
                }
            }
#pragma unroll
            for (int i = 0; i < DIM; i++) {
                if (__popc(i & (i >> 1)) & 1) st[i] = -st[i];
            }
        }

        // Emit fragments: B[k=j][n=g*16+i] = st[i]; lane2 = 4*(i&7) + (j&3),
        // b-reg r = (j>>2)&1 covers k_in_tile = (j&3) + 4r, kt = j>>3.
        const int kt = j >> 3;
        const int r  = (j >> 2) & 1;
#pragma unroll
        for (int i = 0; i < KEEPN; i++) {
            float v   = st[i];
            float hif = __uint_as_float(f2tf32(v));
            float lof = __uint_as_float(f2tf32(v - hif));
            int lane2 = ((i & 7) << 2) | (j & 3);
            int n     = i >> 3;
            int base  = ((g * 4 + kt) * 32 + lane2) * 8 + n * 4;
            shB[base + r]     = hif;
            shB[base + 2 + r] = lof;
        }
    }

    // ---------------- Phase B: per-pixel state (all threads) ----------------
    const int p  = blockIdx.x * 256 + tid;
    const int oy = p >> 9;
    const int ox = p & 511;

    float syf = oy * 0.5f - 0.25f;
    int   y0  = __float2int_rd(syf);
    float fy  = syf - (float)y0;
    int y0c = max(y0, 0);
    int y1c = min(y0 + 1, IW - 1);

    float sxf = ox * 0.5f - 0.25f;
    int   x0  = __float2int_rd(sxf);
    float fx  = sxf - (float)x0;
    int x0c = max(x0, 0);
    int x1c = min(x0 + 1, IW - 1);

    const float* p00 = x + (y0c * IW + x0c) * 5;
    const float* p01 = x + (y0c * IW + x1c) * 5;
    const float* p10 = x + (y1c * IW + x0c) * 5;
    const float* p11 = x + (y1c * IW + x1c) * 5;

    float cc[5], ss[5];
#pragma unroll
    for (int c = 0; c < 5; c++) {
        float v00 = __ldg(p00 + c);
        float v01 = __ldg(p01 + c);
        float v10 = __ldg(p10 + c);
        float v11 = __ldg(p11 + c);
        float top = v00 + fx * (v01 - v00);
        float bot = v10 + fx * (v11 - v10);
        float a   = top + fy * (bot - top);
        float t   = 0.5f * a;                      // t in [0, 0.5]
        float t2  = t * t;
        ss[c] = t * (1.0f + t2 * (-1.0f / 6.0f + t2 * (1.0f / 120.0f)));
        cc[c] = 1.0f + t2 * (-0.5f + t2 * (1.0f / 24.0f + t2 * (-1.0f / 720.0f)));
    }

    {
        float st[DIM];
        float t01[4];
#pragma unroll
        for (int i = 0; i < 4; i++)
            t01[i] = ((i >> 1) ? ss[0] : cc[0]) * ((i & 1) ? ss[1] : cc[1]);
        float t012[8];
#pragma unroll
        for (int i = 0; i < 8; i++)
            t012[i] = t01[i >> 1] * ((i & 1) ? ss[2] : cc[2]);
        float t0123[16];
#pragma unroll
        for (int i = 0; i < 16; i++)
            t0123[i] = t012[i >> 1] * ((i & 1) ? ss[3] : cc[3]);
#pragma unroll
        for (int i = 0; i < DIM; i++)
            st[i] = t0123[i >> 1] * ((i & 1) ? ss[4] : cc[4]);

        // stage state: row = lane, stride SSTRIDE (conflict-free)
        float4* row = reinterpret_cast<float4*>(
            shS + warp * (32 * SSTRIDE) + lane * SSTRIDE);
#pragma unroll
        for (int t = 0; t < 8; t++) {
            float4 v;
            v.x = st[4 * t + 0]; v.y = st[4 * t + 1];
            v.z = st[4 * t + 2]; v.w = st[4 * t + 3];
            row[t] = v;
        }
    }
    __syncthreads();   // W fragments + all states visible

    // ---------------- Phase C: MMA + epilogue ----------------
    const float* Sw = shS + warp * (32 * SSTRIDE);
    const float4* B4 = reinterpret_cast<const float4*>(shB);
    const int warpBase = blockIdx.x * 256 + warp * 32;
    const int colq = 2 * (lane & 3);

#pragma unroll
    for (int m = 0; m < 2; m++) {
        // A fragments (hi/lo tf32 split): 4 k-tiles x 4 regs each
        uint32_t ahi[4][4], alo[4][4];
        {
            const int r0 = m * 16 + (lane >> 2);
            const int c0 = lane & 3;
#pragma unroll
            for (int kt = 0; kt < 4; kt++) {
                float a0 = Sw[r0 * SSTRIDE       + kt * 8 + c0];
                float a1 = Sw[(r0 + 8) * SSTRIDE + kt * 8 + c0];
                float a2 = Sw[r0 * SSTRIDE       + kt * 8 + c0 + 4];
                float a3 = Sw[(r0 + 8) * SSTRIDE + kt * 8 + c0 + 4];
                ahi[kt][0] = f2tf32(a0);
                ahi[kt][1] = f2tf32(a1);
                ahi[kt][2] = f2tf32(a2);
                ahi[kt][3] = f2tf32(a3);
                alo[kt][0] = f2tf32(a0 - __uint_as_float(ahi[kt][0]));
                alo[kt][1] = f2tf32(a1 - __uint_as_float(ahi[kt][1]));
                alo[kt][2] = f2tf32(a2 - __uint_as_float(ahi[kt][2]));
                alo[kt][3] = f2tf32(a3 - __uint_as_float(ahi[kt][3]));
            }
        }

        const int rowA = warpBase + m * 16 + (lane >> 2);
        const int rowB = rowA + 8;

#pragma unroll
        for (int g = 0; g < NGEN; g++) {
            float ca[4] = {0.f, 0.f, 0.f, 0.f};   // n-tile 0: gen cols 0..7
            float cb[4] = {0.f, 0.f, 0.f, 0.f};   // n-tile 1: gen cols 8..15

#pragma unroll
            for (int kt = 0; kt < 4; kt++) {
                const int bidx = ((g * 4 + kt) * 32 + lane) * 2;
                float4 b0 = B4[bidx];        // {hi0,hi1, lo0,lo1} n-tile 0
                float4 b1 = B4[bidx + 1];    // n-tile 1
                uint32_t b0h0 = __float_as_uint(b0.x), b0h1 = __float_as_uint(b0.y);
                uint32_t b0l0 = __float_as_uint(b0.z), b0l1 = __float_as_uint(b0.w);
                uint32_t b1h0 = __float_as_uint(b1.x), b1h1 = __float_as_uint(b1.y);
                uint32_t b1l0 = __float_as_uint(b1.z), b1l1 = __float_as_uint(b1.w);
                MMA_TF32(ca, ahi[kt], b0h0, b0h1);
                MMA_TF32(cb, ahi[kt], b1h0, b1h1);
                MMA_TF32(ca, alo[kt], b0h0, b0h1);
                MMA_TF32(cb, alo[kt], b1h0, b1h1);
                MMA_TF32(ca, ahi[kt], b0l0, b0l1);
                MMA_TF32(cb, ahi[kt], b1l0, b1l1);
            }

            // epilogue: square, per-(row,gen) max over 16 cols, normalize
            float xa0 = ca[0] * ca[0];   // row A, col colq
            float xa1 = ca[1] * ca[1];   // row A, col colq+1
            float xa2 = cb[0] * cb[0];   // row A, col colq+8
            float xa3 = cb[1] * cb[1];   // row A, col colq+9
            float xb0 = ca[2] * ca[2];   // row B
            float xb1 = ca[3] * ca[3];
            float xb2 = cb[2] * cb[2];
            float xb3 = cb[3] * cb[3];

            float ma = fmaxf(fmaxf(xa0, xa1), fmaxf(xa2, xa3));
            float mb = fmaxf(fmaxf(xb0, xb1), fmaxf(xb2, xb3));
            ma = fmaxf(ma, __shfl_xor_sync(0xffffffffu, ma, 1));
            mb = fmaxf(mb, __shfl_xor_sync(0xffffffffu, mb, 1));
            ma = fmaxf(ma, __shfl_xor_sync(0xffffffffu, ma, 2));
            mb = fmaxf(mb, __shfl_xor_sync(0xffffffffu, mb, 2));
            float ia = __fdividef(1.0f, ma);
            float ib = __fdividef(1.0f, mb);

            float* oa = out + ((size_t)g * NPIX + rowA) * KEEPN;
            float* ob = out + ((size_t)g * NPIX + rowB) * KEEPN;
            *reinterpret_cast<float2*>(oa + colq)     = make_float2(xa0 * ia, xa1 * ia);
            *reinterpret_cast<float2*>(oa + colq + 8) = make_float2(xa2 * ia, xa3 * ia);
            *reinterpret_cast<float2*>(ob + colq)     = make_float2(xb0 * ib, xb1 * ib);
            *reinterpret_cast<float2*>(ob + colq + 8) = make_float2(xb2 * ib, xb3 * ib);
        }
    }
}

// ---------------------------------------------------------------------------
extern "C" void kernel_launch(void* const* d_in, const int* in_sizes, int n_in,
                              void* d_out, int out_size)
{
    const float* x  = (const float*)d_in[0];   // [256,256,5]
    const float* qp = (const float*)d_in[1];   // [4,30]
    float* out = (float*)d_out;                // [4,512,512,16]

    const int smem_bytes = (4096 + 8 * 32 * SSTRIDE) * sizeof(float); // 53248
    cudaFuncSetAttribute(qsrgan_fused_kernel,
                         cudaFuncAttributeMaxDynamicSharedMemorySize, smem_bytes);

    qsrgan_fused_kernel<<<NPIX / 256, 256, smem_bytes>>>(x, qp, out);
}

// round 7
// speedup vs baseline: 1.7725x; 1.7725x over previous
#include <cuda_runtime.h>
#include <cuda_bf16.h>
#include <cstdint>

// QSRGAN: x [256,256,5] f32, q_params [4,30] f32 -> out [4,512,512,16] f32.
//
// Single fused kernel (spill-safe rework of R5):
//  Phase A (threads 0-127): evolve 32 basis columns through the 6-layer RY+CZ
//    circuit for all 4 generators (poly sincos); emit W rows 0..15 as tf32
//    hi/lo mma B-fragments into smem. Redundant per block; avoids a separate
//    kernel + launch gap.
//  Phase B (all threads): bilinear upsample, poly sincos, rank-1 product
//    state streamed straight into smem (no st[32] register array).
//  Phase C: per warp = 32 pixels, two m16 tiles (NOT unrolled -> one tile's
//    fragments live at a time); per generator accumulate [16x32]x[32x16] via
//    mma.sync.m16n8k8.tf32 with 3-term hi/lo split (fp32 accuracy).
//    Epilogue: square, quad-shuffle max, normalize, store.
//  (sum-normalization cancels: p/sum/max(p/sum) = p/max(p))

#define DIM 32
#define KEEPN 16
#define NGEN 4
#define IW 256
#define NPIX (512*512)
#define SSTRIDE 36          // state staging row stride (floats): conflict-free reads

__device__ __forceinline__ uint32_t f2tf32(float x) {
    uint32_t u;
    asm("cvt.rna.tf32.f32 %0, %1;" : "=r"(u) : "f"(x));
    return u;
}

// sin/cos of t in [0, 0.5] via Taylor (err < 1e-9)
__device__ __forceinline__ void poly_sincos(float t, float& s, float& c) {
    float t2 = t * t;
    s = t * (1.0f + t2 * (-1.0f / 6.0f + t2 * (1.0f / 120.0f)));
    c = 1.0f + t2 * (-0.5f + t2 * (1.0f / 24.0f + t2 * (-1.0f / 720.0f)));
}

#define MMA_TF32(C, A, B0, B1)                                                 \
    asm volatile("mma.sync.aligned.m16n8k8.row.col.f32.tf32.tf32.f32 "         \
                 "{%0,%1,%2,%3}, {%4,%5,%6,%7}, {%8,%9}, {%0,%1,%2,%3};"       \
                 : "+f"((C)[0]), "+f"((C)[1]), "+f"((C)[2]), "+f"((C)[3])      \
                 : "r"((A)[0]), "r"((A)[1]), "r"((A)[2]), "r"((A)[3]),         \
                   "r"(B0), "r"(B1))

__global__ void __launch_bounds__(256, 3) qsrgan_fused_kernel(
    const float* __restrict__ x, const float* __restrict__ qp,
    float* __restrict__ out)
{
    extern __shared__ float smem[];
    float* shB = smem;                 // 4096 floats: B fragments (hi/lo paired)
    float* shS = smem + 4096;          // 8 warps * 32 rows * SSTRIDE floats

    const int tid  = threadIdx.x;
    const int lane = tid & 31;
    const int warp = tid >> 5;

    // ---------------- Phase A: W fragments (threads 0..127) ----------------
    if (tid < 128) {
        const int g = tid >> 5;        // generator
        const int j = tid & 31;        // basis column (= GEMM k index)

        float st[DIM];
#pragma unroll
        for (int i = 0; i < DIM; i++) st[i] = (i == j) ? 1.0f : 0.0f;

#pragma unroll 1
        for (int d = 0; d < 6; d++) {
#pragma unroll
            for (int q = 0; q < 5; q++) {
                float s, c;
                poly_sincos(0.5f * qp[g * 30 + d * 5 + q], s, c);
                const int r = 1 << (4 - q);
#pragma unroll
                for (int i = 0; i < DIM; i++) {
                    if ((i & r) == 0) {
                        float a0 = st[i];
                        float a1 = st[i | r];
                        st[i]     = c * a0 - s * a1;
                        st[i | r] = s * a0 + c * a1;
                    }
                }
            }
#pragma unroll
            for (int i = 0; i < DIM; i++) {
                if (__popc(i & (i >> 1)) & 1) st[i] = -st[i];
            }
        }

        // Emit fragments: B[k=j][n=g*16+i] = st[i].
        // layout: base = ((g*4+kt)*32 + lane2)*8 + n4*4; [hi0,hi1,lo0,lo1]
        const int kt = j >> 3;
        const int r  = (j >> 2) & 1;
#pragma unroll
        for (int i = 0; i < KEEPN; i++) {
            float v   = st[i];
            float hif = __uint_as_float(f2tf32(v));
            float lof = __uint_as_float(f2tf32(v - hif));
            int lane2 = ((i & 7) << 2) | (j & 3);
            int base  = ((g * 4 + kt) * 32 + lane2) * 8 + (i >> 3) * 4;
            shB[base + r]     = hif;
            shB[base + 2 + r] = lof;
        }
    }

    // ---------------- Phase B: per-pixel state (all threads) ----------------
    const int p  = blockIdx.x * 256 + tid;
    const int oy = p >> 9;
    const int ox = p & 511;

    float syf = oy * 0.5f - 0.25f;
    int   y0  = __float2int_rd(syf);
    float fy  = syf - (float)y0;
    int y0c = max(y0, 0);
    int y1c = min(y0 + 1, IW - 1);

    float sxf = ox * 0.5f - 0.25f;
    int   x0  = __float2int_rd(sxf);
    float fx  = sxf - (float)x0;
    int x0c = max(x0, 0);
    int x1c = min(x0 + 1, IW - 1);

    const float* p00 = x + (y0c * IW + x0c) * 5;
    const float* p01 = x + (y0c * IW + x1c) * 5;
    const float* p10 = x + (y1c * IW + x0c) * 5;
    const float* p11 = x + (y1c * IW + x1c) * 5;

    float cc[5], ss[5];
#pragma unroll
    for (int c = 0; c < 5; c++) {
        float v00 = __ldg(p00 + c);
        float v01 = __ldg(p01 + c);
        float v10 = __ldg(p10 + c);
        float v11 = __ldg(p11 + c);
        float top = v00 + fx * (v01 - v00);
        float bot = v10 + fx * (v11 - v10);
        float a   = top + fy * (bot - top);
        poly_sincos(0.5f * a, ss[c], cc[c]);     // a in [0,1) -> t in [0,0.5]
    }

    {
        // build t0123[16], then stream final 32 amplitudes to smem as float2
        float t01[4];
#pragma unroll
        for (int i = 0; i < 4; i++)
            t01[i] = ((i >> 1) ? ss[0] : cc[0]) * ((i & 1) ? ss[1] : cc[1]);
        float t012[8];
#pragma unroll
        for (int i = 0; i < 8; i++)
            t012[i] = t01[i >> 1] * ((i & 1) ? ss[2] : cc[2]);
        float t0123[16];
#pragma unroll
        for (int i = 0; i < 16; i++)
            t0123[i] = t012[i >> 1] * ((i & 1) ? ss[3] : cc[3]);

        float2* row = reinterpret_cast<float2*>(
            shS + warp * (32 * SSTRIDE) + lane * SSTRIDE);
        float c4 = cc[4], s4 = ss[4];
#pragma unroll
        for (int i = 0; i < 16; i++)
            row[i] = make_float2(t0123[i] * c4, t0123[i] * s4);
    }
    __syncthreads();   // W fragments + all states visible

    // ---------------- Phase C: MMA + epilogue ----------------
    const float* Sw = shS + warp * (32 * SSTRIDE);
    const float4* B4 = reinterpret_cast<const float4*>(shB);
    const int warpBase = blockIdx.x * 256 + warp * 32;
    const int colq = 2 * (lane & 3);

#pragma unroll 1
    for (int m = 0; m < 2; m++) {
        // A fragments (hi/lo tf32 split): 4 k-tiles x 4 regs each
        uint32_t ahi[4][4], alo[4][4];
        {
            const int r0 = m * 16 + (lane >> 2);
            const int c0 = lane & 3;
#pragma unroll
            for (int kt = 0; kt < 4; kt++) {
                float a0 = Sw[r0 * SSTRIDE       + kt * 8 + c0];
                float a1 = Sw[(r0 + 8) * SSTRIDE + kt * 8 + c0];
                float a2 = Sw[r0 * SSTRIDE       + kt * 8 + c0 + 4];
                float a3 = Sw[(r0 + 8) * SSTRIDE + kt * 8 + c0 + 4];
                ahi[kt][0] = f2tf32(a0);
                ahi[kt][1] = f2tf32(a1);
                ahi[kt][2] = f2tf32(a2);
                ahi[kt][3] = f2tf32(a3);
                alo[kt][0] = f2tf32(a0 - __uint_as_float(ahi[kt][0]));
                alo[kt][1] = f2tf32(a1 - __uint_as_float(ahi[kt][1]));
                alo[kt][2] = f2tf32(a2 - __uint_as_float(ahi[kt][2]));
                alo[kt][3] = f2tf32(a3 - __uint_as_float(ahi[kt][3]));
            }
        }

        const int rowA = warpBase + m * 16 + (lane >> 2);
        const int rowB = rowA + 8;

#pragma unroll
        for (int g = 0; g < NGEN; g++) {
            float ca[4] = {0.f, 0.f, 0.f, 0.f};   // n-tile 0: gen cols 0..7
            float cb[4] = {0.f, 0.f, 0.f, 0.f};   // n-tile 1: gen cols 8..15

#pragma unroll
            for (int kt = 0; kt < 4; kt++) {
                const int bidx = ((g * 4 + kt) * 32 + lane) * 2;
                float4 b0 = B4[bidx];        // {hi0,hi1, lo0,lo1} n-tile 0
                float4 b1 = B4[bidx + 1];    // n-tile 1
                uint32_t b0h0 = __float_as_uint(b0.x), b0h1 = __float_as_uint(b0.y);
                uint32_t b0l0 = __float_as_uint(b0.z), b0l1 = __float_as_uint(b0.w);
                uint32_t b1h0 = __float_as_uint(b1.x), b1h1 = __float_as_uint(b1.y);
                uint32_t b1l0 = __float_as_uint(b1.z), b1l1 = __float_as_uint(b1.w);
                MMA_TF32(ca, ahi[kt], b0h0, b0h1);
                MMA_TF32(cb, ahi[kt], b1h0, b1h1);
                MMA_TF32(ca, alo[kt], b0h0, b0h1);
                MMA_TF32(cb, alo[kt], b1h0, b1h1);
                MMA_TF32(ca, ahi[kt], b0l0, b0l1);
                MMA_TF32(cb, ahi[kt], b1l0, b1l1);
            }

            // epilogue: square, per-(row,gen) max over 16 cols, normalize
            float xa0 = ca[0] * ca[0];
            float xa1 = ca[1] * ca[1];
            float xa2 = cb[0] * cb[0];
            float xa3 = cb[1] * cb[1];
            float xb0 = ca[2] * ca[2];
            float xb1 = ca[3] * ca[3];
            float xb2 = cb[2] * cb[2];
            float xb3 = cb[3] * cb[3];

            float ma = fmaxf(fmaxf(xa0, xa1), fmaxf(xa2, xa3));
            float mb = fmaxf(fmaxf(xb0, xb1), fmaxf(xb2, xb3));
            ma = fmaxf(ma, __shfl_xor_sync(0xffffffffu, ma, 1));
            mb = fmaxf(mb, __shfl_xor_sync(0xffffffffu, mb, 1));
            ma = fmaxf(ma, __shfl_xor_sync(0xffffffffu, ma, 2));
            mb = fmaxf(mb, __shfl_xor_sync(0xffffffffu, mb, 2));
            float ia = __fdividef(1.0f, ma);
            float ib = __fdividef(1.0f, mb);

            float* oa = out + ((size_t)g * NPIX + rowA) * KEEPN;
            float* ob = out + ((size_t)g * NPIX + rowB) * KEEPN;
            *reinterpret_cast<float2*>(oa + colq)     = make_float2(xa0 * ia, xa1 * ia);
            *reinterpret_cast<float2*>(oa + colq + 8) = make_float2(xa2 * ia, xa3 * ia);
            *reinterpret_cast<float2*>(ob + colq)     = make_float2(xb0 * ib, xb1 * ib);
            *reinterpret_cast<float2*>(ob + colq + 8) = make_float2(xb2 * ib, xb3 * ib);
        }
    }
}

// ---------------------------------------------------------------------------
extern "C" void kernel_launch(void* const* d_in, const int* in_sizes, int n_in,
                              void* d_out, int out_size)
{
    const float* x  = (const float*)d_in[0];   // [256,256,5]
    const float* qp = (const float*)d_in[1];   // [4,30]
    float* out = (float*)d_out;                // [4,512,512,16]

    const int smem_bytes = (4096 + 8 * 32 * SSTRIDE) * sizeof(float); // 53248
    cudaFuncSetAttribute(qsrgan_fused_kernel,
                         cudaFuncAttributeMaxDynamicSharedMemorySize, smem_bytes);

    qsrgan_fused_kernel<<<NPIX / 256, 256, smem_bytes>>>(x, qp, out);
}

// round 9
// speedup vs baseline: 1.9490x; 1.0996x over previous
#include <cuda_runtime.h>
#include <cuda_bf16.h>
#include <cstdint>

// QSRGAN: x [256,256,5] f32, q_params [4,30] f32 -> out [4,512,512,16] f32.
//
// Two kernels (R3 structure) with R7's low-register main phase:
//  Kernel 1 (tiny, runs once): evolve 32 basis columns through the 6-layer
//    RY+CZ circuit per generator; emit W rows 0..15 as tf32 hi/lo mma
//    B-fragments (paired float4 layout) into g_Bfrag.
//  Kernel 2: copy fragments to smem; per pixel bilinear upsample + poly
//    sincos + rank-1 product state streamed to smem; per warp = 32 pixels,
//    two m16 tiles (m-loop NOT unrolled -> one tile's fragments live at a
//    time -> 80 regs -> 3 blocks/SM); per generator [16x32]x[32x16] via
//    mma.sync.m16n8k8.tf32 with 3-term hi/lo split (fp32 accuracy).
//    Epilogue: square, quad-shuffle max, normalize, store.
//  (sum-normalization cancels: p/sum/max(p/sum) = p/max(p))
//
// B fragment layout (float units): base = ((g*4+kt)*32 + lane)*8 + ntile*4,
// holding [hi_r0, hi_r1, lo_r0, lo_r1] -> one LDS.128 per (g,kt,ntile).

#define DIM 32
#define KEEPN 16
#define NGEN 4
#define IW 256
#define NPIX (512*512)
#define SSTRIDE 36          // state staging row stride: conflict-free Phase-C reads

__device__ float g_Bfrag[4096];

__device__ __forceinline__ uint32_t f2tf32(float x) {
    uint32_t u;
    asm("cvt.rna.tf32.f32 %0, %1;" : "=r"(u) : "f"(x));
    return u;
}

// sin/cos of t in [0, 0.5] via Taylor (err < 1e-9)
__device__ __forceinline__ void poly_sincos(float t, float& s, float& c) {
    float t2 = t * t;
    s = t * (1.0f + t2 * (-1.0f / 6.0f + t2 * (1.0f / 120.0f)));
    c = 1.0f + t2 * (-0.5f + t2 * (1.0f / 24.0f + t2 * (-1.0f / 720.0f)));
}

#define MMA_TF32(C, A, B0, B1)                                                 \
    asm volatile("mma.sync.aligned.m16n8k8.row.col.f32.tf32.tf32.f32 "         \
                 "{%0,%1,%2,%3}, {%4,%5,%6,%7}, {%8,%9}, {%0,%1,%2,%3};"       \
                 : "+f"((C)[0]), "+f"((C)[1]), "+f"((C)[2]), "+f"((C)[3])      \
                 : "r"((A)[0]), "r"((A)[1]), "r"((A)[2]), "r"((A)[3]),         \
                   "r"(B0), "r"(B1))

// ---------------------------------------------------------------------------
// Kernel 1: precompute circuit matrix fragments (1 block x 128 threads)
// ---------------------------------------------------------------------------
__global__ void precompute_W_kernel(const float* __restrict__ qp)
{
    const int g = threadIdx.x >> 5;    // generator
    const int j = threadIdx.x & 31;    // basis column (= GEMM k index)

    float st[DIM];
#pragma unroll
    for (int i = 0; i < DIM; i++) st[i] = (i == j) ? 1.0f : 0.0f;

#pragma unroll 1
    for (int d = 0; d < 6; d++) {
#pragma unroll
        for (int q = 0; q < 5; q++) {
            float th = 0.5f * qp[g * 30 + d * 5 + q];
            float s, c;
            sincosf(th, &s, &c);
            const int r = 1 << (4 - q);
#pragma unroll
            for (int i = 0; i < DIM; i++) {
                if ((i & r) == 0) {
                    float a0 = st[i];
                    float a1 = st[i | r];
                    st[i]     = c * a0 - s * a1;
                    st[i | r] = s * a0 + c * a1;
                }
            }
        }
#pragma unroll
        for (int i = 0; i < DIM; i++) {
            if (__popc(i & (i >> 1)) & 1) st[i] = -st[i];
        }
    }

    // Emit fragments: B[k=j][n=g*16+i] = st[i].
    const int kt = j >> 3;
    const int r  = (j >> 2) & 1;
#pragma unroll
    for (int i = 0; i < KEEPN; i++) {
        float v   = st[i];
        float hif = __uint_as_float(f2tf32(v));
        float lof = __uint_as_float(f2tf32(v - hif));
        int lane2 = ((i & 7) << 2) | (j & 3);
        int base  = ((g * 4 + kt) * 32 + lane2) * 8 + (i >> 3) * 4;
        g_Bfrag[base + r]     = hif;
        g_Bfrag[base + 2 + r] = lof;
    }
}

// ---------------------------------------------------------------------------
// Kernel 2: main kernel. 1024 blocks x 256 threads, each warp = 32 pixels.
// ---------------------------------------------------------------------------
__global__ void __launch_bounds__(256, 3) qsrgan_mma_kernel(
    const float* __restrict__ x, float* __restrict__ out)
{
    extern __shared__ float smem[];
    float* shB = smem;                 // 4096 floats: B fragments (hi/lo paired)
    float* shS = smem + 4096;          // 8 warps * 32 rows * SSTRIDE floats

    const int tid  = threadIdx.x;
    const int lane = tid & 31;
    const int warp = tid >> 5;

    // cooperative copy of B fragments (16 KB)
    {
        const float4* src = reinterpret_cast<const float4*>(g_Bfrag);
        float4* dst = reinterpret_cast<float4*>(shB);
#pragma unroll
        for (int t = 0; t < 4; t++) dst[tid + 256 * t] = src[tid + 256 * t];
    }

    // ---------------- Phase B: per-pixel state ----------------
    const int p  = blockIdx.x * 256 + tid;
    const int oy = p >> 9;
    const int ox = p & 511;

    float syf = oy * 0.5f - 0.25f;
    int   y0  = __float2int_rd(syf);
    float fy  = syf - (float)y0;
    int y0c = max(y0, 0);
    int y1c = min(y0 + 1, IW - 1);

    float sxf = ox * 0.5f - 0.25f;
    int   x0  = __float2int_rd(sxf);
    float fx  = sxf - (float)x0;
    int x0c = max(x0, 0);
    int x1c = min(x0 + 1, IW - 1);

    const float* p00 = x + (y0c * IW + x0c) * 5;
    const float* p01 = x + (y0c * IW + x1c) * 5;
    const float* p10 = x + (y1c * IW + x0c) * 5;
    const float* p11 = x + (y1c * IW + x1c) * 5;

    float cc[5], ss[5];
#pragma unroll
    for (int c = 0; c < 5; c++) {
        float v00 = __ldg(p00 + c);
        float v01 = __ldg(p01 + c);
        float v10 = __ldg(p10 + c);
        float v11 = __ldg(p11 + c);
        float top = v00 + fx * (v01 - v00);
        float bot = v10 + fx * (v11 - v10);
        float a   = top + fy * (bot - top);
        poly_sincos(0.5f * a, ss[c], cc[c]);     // a in [0,1) -> t in [0,0.5]
    }

    {
        // build t0123[16], stream final 32 amplitudes to smem as float2
        float t01[4];
#pragma unroll
        for (int i = 0; i < 4; i++)
            t01[i] = ((i >> 1) ? ss[0] : cc[0]) * ((i & 1) ? ss[1] : cc[1]);
        float t012[8];
#pragma unroll
        for (int i = 0; i < 8; i++)
            t012[i] = t01[i >> 1] * ((i & 1) ? ss[2] : cc[2]);
        float t0123[16];
#pragma unroll
        for (int i = 0; i < 16; i++)
            t0123[i] = t012[i >> 1] * ((i & 1) ? ss[3] : cc[3]);

        float2* row = reinterpret_cast<float2*>(
            shS + warp * (32 * SSTRIDE) + lane * SSTRIDE);
        float c4 = cc[4], s4 = ss[4];
#pragma unroll
        for (int i = 0; i < 16; i++)
            row[i] = make_float2(t0123[i] * c4, t0123[i] * s4);
    }
    __syncthreads();   // B fragments + all states visible

    // ---------------- Phase C: MMA + epilogue ----------------
    const float* Sw = shS + warp * (32 * SSTRIDE);
    const float4* B4 = reinterpret_cast<const float4*>(shB);
    const int warpBase = blockIdx.x * 256 + warp * 32;
    const int colq = 2 * (lane & 3);

#pragma unroll 1
    for (int m = 0; m < 2; m++) {
        // A fragments (hi/lo tf32 split): 4 k-tiles x 4 regs each
        uint32_t ahi[4][4], alo[4][4];
        {
            const int r0 = m * 16 + (lane >> 2);
            const int c0 = lane & 3;
#pragma unroll
            for (int kt = 0; kt < 4; kt++) {
                float a0 = Sw[r0 * SSTRIDE       + kt * 8 + c0];
                float a1 = Sw[(r0 + 8) * SSTRIDE + kt * 8 + c0];
                float a2 = Sw[r0 * SSTRIDE       + kt * 8 + c0 + 4];
                float a3 = Sw[(r0 + 8) * SSTRIDE + kt * 8 + c0 + 4];
                ahi[kt][0] = f2tf32(a0);
                ahi[kt][1] = f2tf32(a1);
                ahi[kt][2] = f2tf32(a2);
                ahi[kt][3] = f2tf32(a3);
                alo[kt][0] = f2tf32(a0 - __uint_as_float(ahi[kt][0]));
                alo[kt][1] = f2tf32(a1 - __uint_as_float(ahi[kt][1]));
                alo[kt][2] = f2tf32(a2 - __uint_as_float(ahi[kt][2]));
                alo[kt][3] = f2tf32(a3 - __uint_as_float(ahi[kt][3]));
            }
        }

        const int rowA = warpBase + m * 16 + (lane >> 2);
        const int rowB = rowA + 8;

#pragma unroll
        for (int g = 0; g < NGEN; g++) {
            float ca[4] = {0.f, 0.f, 0.f, 0.f};   // n-tile 0: gen cols 0..7
            float cb[4] = {0.f, 0.f, 0.f, 0.f};   // n-tile 1: gen cols 8..15

#pragma unroll
            for (int kt = 0; kt < 4; kt++) {
                const int bidx = ((g * 4 + kt) * 32 + lane) * 2;
                float4 b0 = B4[bidx];        // {hi0,hi1, lo0,lo1} n-tile 0
                float4 b1 = B4[bidx + 1];    // n-tile 1
                uint32_t b0h0 = __float_as_uint(b0.x), b0h1 = __float_as_uint(b0.y);
                uint32_t b0l0 = __float_as_uint(b0.z), b0l1 = __float_as_uint(b0.w);
                uint32_t b1h0 = __float_as_uint(b1.x), b1h1 = __float_as_uint(b1.y);
                uint32_t b1l0 = __float_as_uint(b1.z), b1l1 = __float_as_uint(b1.w);
                MMA_TF32(ca, ahi[kt], b0h0, b0h1);
                MMA_TF32(cb, ahi[kt], b1h0, b1h1);
                MMA_TF32(ca, alo[kt], b0h0, b0h1);
                MMA_TF32(cb, alo[kt], b1h0, b1h1);
                MMA_TF32(ca, ahi[kt], b0l0, b0l1);
                MMA_TF32(cb, ahi[kt], b1l0, b1l1);
            }

            // epilogue: square, per-(row,gen) max over 16 cols, normalize
            float xa0 = ca[0] * ca[0];
            float xa1 = ca[1] * ca[1];
            float xa2 = cb[0] * cb[0];
            float xa3 = cb[1] * cb[1];
            float xb0 = ca[2] * ca[2];
            float xb1 = ca[3] * ca[3];
            float xb2 = cb[2] * cb[2];
            float xb3 = cb[3] * cb[3];

            float ma = fmaxf(fmaxf(xa0, xa1), fmaxf(xa2, xa3));
            float mb = fmaxf(fmaxf(xb0, xb1), fmaxf(xb2, xb3));
            ma = fmaxf(ma, __shfl_xor_sync(0xffffffffu, ma, 1));
            mb = fmaxf(mb, __shfl_xor_sync(0xffffffffu, mb, 1));
            ma = fmaxf(ma, __shfl_xor_sync(0xffffffffu, ma, 2));
            mb = fmaxf(mb, __shfl_xor_sync(0xffffffffu, mb, 2));
            float ia = __fdividef(1.0f, ma);
            float ib = __fdividef(1.0f, mb);

            float* oa = out + ((size_t)g * NPIX + rowA) * KEEPN;
            float* ob = out + ((size_t)g * NPIX + rowB) * KEEPN;
            *reinterpret_cast<float2*>(oa + colq)     = make_float2(xa0 * ia, xa1 * ia);
            *reinterpret_cast<float2*>(oa + colq + 8) = make_float2(xa2 * ia, xa3 * ia);
            *reinterpret_cast<float2*>(ob + colq)     = make_float2(xb0 * ib, xb1 * ib);
            *reinterpret_cast<float2*>(ob + colq + 8) = make_float2(xb2 * ib, xb3 * ib);
        }
    }
}

// ---------------------------------------------------------------------------
extern "C" void kernel_launch(void* const* d_in, const int* in_sizes, int n_in,
                              void* d_out, int out_size)
{
    const float* x  = (const float*)d_in[0];   // [256,256,5]
    const float* qp = (const float*)d_in[1];   // [4,30]
    float* out = (float*)d_out;                // [4,512,512,16]

    const int smem_bytes = (4096 + 8 * 32 * SSTRIDE) * sizeof(float); // 53248
    cudaFuncSetAttribute(qsrgan_mma_kernel,
                         cudaFuncAttributeMaxDynamicSharedMemorySize, smem_bytes);

    precompute_W_kernel<<<1, 128>>>(qp);
    qsrgan_mma_kernel<<<NPIX / 256, 256, smem_bytes>>>(x, out);
}

// round 10
// speedup vs baseline: 2.9937x; 1.5360x over previous
#include <cuda_runtime.h>
#include <cuda_bf16.h>
#include <cstdint>

// QSRGAN: x [256,256,5] f32, q_params [4,30] f32 -> out [4,512,512,16] f32.
//
// Two kernels, bf16 3-term-split MMA (m16n8k16):
//  Kernel 1 (runs once): evolve 32 basis columns through the 6-layer RY+CZ
//    circuit per generator; emit W rows 0..15 as bf16 hi/lo mma B-fragments.
//  Kernel 2: copy fragments to smem (8KB); per pixel bilinear upsample + poly
//    sincos; stage the rank-1 product state TRANSPOSED (S^T[k][pixel], stride
//    36 -> conflict-free stores AND fragment reads); per warp = 32 pixels,
//    two m16 tiles; per generator accumulate [16x32]x[32x16] with
//    mma.sync.m16n8k16.row.col.f32.bf16.bf16.f32, 3-term hi/lo split:
//    AhiBhi + AloBhi + AhiBlo (err ~2^-17, well under 1e-3 threshold).
//    Epilogue: square, quad-shuffle max, normalize, store.
//  (sum-normalization cancels: p/sum/max(p/sum) = p/max(p))
//
// B fragment layout (bf16 units): for g(0..3), kt(0..1), lane(0..31):
//   float4 index (g*2+kt)*32 + lane holds {nt0_b0, nt0_b1, nt1_b0, nt1_b1}
//   (each element a packed bf16x2); hi array = first 256 float4, lo = next.
//   Lane stride 16B -> conflict-free LDS.128.

#define DIM 32
#define KEEPN 16
#define NGEN 4
#define IW 256
#define NPIX (512*512)
#define TSTRIDE 36     // S^T row stride (floats): 36 mod 32 = 4 -> conflict-free

__device__ __align__(16) __nv_bfloat16 g_Bfrag[4096];   // hi[2048], lo[2048]

// sin/cos of t in [0, 0.5] via Taylor (err < 1e-9)
__device__ __forceinline__ void poly_sincos(float t, float& s, float& c) {
    float t2 = t * t;
    s = t * (1.0f + t2 * (-1.0f / 6.0f + t2 * (1.0f / 120.0f)));
    c = 1.0f + t2 * (-0.5f + t2 * (1.0f / 24.0f + t2 * (-1.0f / 720.0f)));
}

// pack two floats into bf16x2: lower half = even-k element
__device__ __forceinline__ uint32_t pack_bf16x2(float even, float odd) {
    uint32_t d;
    asm("cvt.rn.bf16x2.f32 %0, %1, %2;" : "=r"(d) : "f"(odd), "f"(even));
    return d;
}

#define MMA_BF16(C, A, B0, B1)                                                 \
    asm volatile("mma.sync.aligned.m16n8k16.row.col.f32.bf16.bf16.f32 "        \
                 "{%0,%1,%2,%3}, {%4,%5,%6,%7}, {%8,%9}, {%0,%1,%2,%3};"       \
                 : "+f"((C)[0]), "+f"((C)[1]), "+f"((C)[2]), "+f"((C)[3])      \
                 : "r"((A)[0]), "r"((A)[1]), "r"((A)[2]), "r"((A)[3]),         \
                   "r"(B0), "r"(B1))

// ---------------------------------------------------------------------------
// Kernel 1: precompute circuit matrix fragments (1 block x 128 threads)
// ---------------------------------------------------------------------------
__global__ void precompute_W_kernel(const float* __restrict__ qp)
{
    const int g = threadIdx.x >> 5;    // generator
    const int j = threadIdx.x & 31;    // basis column (= GEMM k index)

    float st[DIM];
#pragma unroll
    for (int i = 0; i < DIM; i++) st[i] = (i == j) ? 1.0f : 0.0f;

#pragma unroll 1
    for (int d = 0; d < 6; d++) {
#pragma unroll
        for (int q = 0; q < 5; q++) {
            float th = 0.5f * qp[g * 30 + d * 5 + q];
            float s, c;
            sincosf(th, &s, &c);
            const int r = 1 << (4 - q);
#pragma unroll
            for (int i = 0; i < DIM; i++) {
                if ((i & r) == 0) {
                    float a0 = st[i];
                    float a1 = st[i | r];
                    st[i]     = c * a0 - s * a1;
                    st[i | r] = s * a0 + c * a1;
                }
            }
        }
#pragma unroll
        for (int i = 0; i < DIM; i++) {
            if (__popc(i & (i >> 1)) & 1) st[i] = -st[i];
        }
    }

    // Emit fragments. B[k=j][n=g*16+i] = st[i].
    // j -> kt = j>>4, kk = j&15, r8 = kk>>3 (b0/b1), c = (kk>>1)&3, par = kk&1
    // i -> ntile = i>>3, groupID = i&7; lane = 4*groupID + c
    const int kt  = j >> 4;
    const int kk  = j & 15;
    const int r8  = kk >> 3;
    const int c   = (kk >> 1) & 3;
    const int par = kk & 1;
#pragma unroll
    for (int i = 0; i < KEEPN; i++) {
        float v = st[i];
        __nv_bfloat16 hi = __float2bfloat16(v);
        __nv_bfloat16 lo = __float2bfloat16(v - __bfloat162float(hi));
        int lane = 4 * (i & 7) + c;
        int elem = (i >> 3) * 2 + r8;
        int idx  = (((g * 2 + kt) * 32 + lane) * 4 + elem) * 2 + par;
        g_Bfrag[idx]        = hi;
        g_Bfrag[2048 + idx] = lo;
    }
}

// ---------------------------------------------------------------------------
// Kernel 2: main kernel. 1024 blocks x 256 threads, each warp = 32 pixels.
// smem: 2048 floats B fragments (8KB) + 8*32*TSTRIDE floats S^T (36KB)
// ---------------------------------------------------------------------------
__global__ void __launch_bounds__(256, 3) qsrgan_mma_kernel(
    const float* __restrict__ x, float* __restrict__ out)
{
    extern __shared__ float smem[];
    float* shB = smem;                 // 2048 floats = 4096 bf16 (hi then lo)
    float* shS = smem + 2048;          // S^T per warp: 32 k-rows x stride 36

    const int tid  = threadIdx.x;
    const int lane = tid & 31;
    const int warp = tid >> 5;

    // cooperative copy of B fragments (8 KB = 512 float4)
    {
        const float4* src = reinterpret_cast<const float4*>(g_Bfrag);
        float4* dst = reinterpret_cast<float4*>(shB);
        dst[tid]       = src[tid];
        dst[tid + 256] = src[tid + 256];
    }

    // ---------------- Phase B: per-pixel state ----------------
    const int p  = blockIdx.x * 256 + tid;
    const int oy = p >> 9;
    const int ox = p & 511;

    float syf = oy * 0.5f - 0.25f;
    int   y0  = __float2int_rd(syf);
    float fy  = syf - (float)y0;
    int y0c = max(y0, 0);
    int y1c = min(y0 + 1, IW - 1);

    float sxf = ox * 0.5f - 0.25f;
    int   x0  = __float2int_rd(sxf);
    float fx  = sxf - (float)x0;
    int x0c = max(x0, 0);
    int x1c = min(x0 + 1, IW - 1);

    const float* p00 = x + (y0c * IW + x0c) * 5;
    const float* p01 = x + (y0c * IW + x1c) * 5;
    const float* p10 = x + (y1c * IW + x0c) * 5;
    const float* p11 = x + (y1c * IW + x1c) * 5;

    float cc[5], ss[5];
#pragma unroll
    for (int c = 0; c < 5; c++) {
        float v00 = __ldg(p00 + c);
        float v01 = __ldg(p01 + c);
        float v10 = __ldg(p10 + c);
        float v11 = __ldg(p11 + c);
        float top = v00 + fx * (v01 - v00);
        float bot = v10 + fx * (v11 - v10);
        float a   = top + fy * (bot - top);
        poly_sincos(0.5f * a, ss[c], cc[c]);     // a in [0,1) -> t in [0,0.5]
    }

    {
        // build t0123[16]; stream 32 amplitudes TRANSPOSED: S^T[k][lane]
        float t01[4];
#pragma unroll
        for (int i = 0; i < 4; i++)
            t01[i] = ((i >> 1) ? ss[0] : cc[0]) * ((i & 1) ? ss[1] : cc[1]);
        float t012[8];
#pragma unroll
        for (int i = 0; i < 8; i++)
            t012[i] = t01[i >> 1] * ((i & 1) ? ss[2] : cc[2]);
        float t0123[16];
#pragma unroll
        for (int i = 0; i < 16; i++)
            t0123[i] = t012[i >> 1] * ((i & 1) ? ss[3] : cc[3]);

        float* Sw = shS + warp * (32 * TSTRIDE) + lane;
        float c4 = cc[4], s4 = ss[4];
#pragma unroll
        for (int i = 0; i < 16; i++) {
            Sw[(2 * i)     * TSTRIDE] = t0123[i] * c4;   // k even
            Sw[(2 * i + 1) * TSTRIDE] = t0123[i] * s4;   // k odd
        }
    }
    __syncthreads();   // B fragments + all states visible

    // ---------------- Phase C: MMA + epilogue ----------------
    const float* Sw = shS + warp * (32 * TSTRIDE);
    const float4* Bhi4 = reinterpret_cast<const float4*>(shB);
    const float4* Blo4 = Bhi4 + 256;
    const int warpBase = blockIdx.x * 256 + warp * 32;
    const int colq = 2 * (lane & 3);

#pragma unroll 1
    for (int m = 0; m < 2; m++) {
        // A fragments (bf16 hi/lo split): 2 k-tiles x 4 regs each
        uint32_t ahi[2][4], alo[2][4];
        {
            const int r0 = m * 16 + (lane >> 2);
            const int c0 = lane & 3;
#pragma unroll
            for (int kt = 0; kt < 2; kt++) {
                const int kb = kt * 16 + 2 * c0;
#pragma unroll
                for (int rg = 0; rg < 4; rg++) {
                    // rg: 0 -> (r0, k), 1 -> (r0+8, k), 2 -> (r0, k+8), 3 -> (r0+8, k+8)
                    int row = r0 + (rg & 1) * 8;
                    int kof = kb + (rg >> 1) * 8;
                    float fe = Sw[kof * TSTRIDE + row];
                    float fo = Sw[(kof + 1) * TSTRIDE + row];
                    uint32_t h = pack_bf16x2(fe, fo);
                    float he = __uint_as_float(h << 16);
                    float ho = __uint_as_float(h & 0xffff0000u);
                    ahi[kt][rg] = h;
                    alo[kt][rg] = pack_bf16x2(fe - he, fo - ho);
                }
            }
        }

        const int rowA = warpBase + m * 16 + (lane >> 2);
        const int rowB = rowA + 8;

#pragma unroll
        for (int g = 0; g < NGEN; g++) {
            float ca[4] = {0.f, 0.f, 0.f, 0.f};   // n-tile 0: gen cols 0..7
            float cb[4] = {0.f, 0.f, 0.f, 0.f};   // n-tile 1: gen cols 8..15

#pragma unroll
            for (int kt = 0; kt < 2; kt++) {
                const int bidx = (g * 2 + kt) * 32 + lane;
                float4 bh = Bhi4[bidx];   // {nt0_b0, nt0_b1, nt1_b0, nt1_b1}
                float4 bl = Blo4[bidx];
                uint32_t bh00 = __float_as_uint(bh.x), bh01 = __float_as_uint(bh.y);
                uint32_t bh10 = __float_as_uint(bh.z), bh11 = __float_as_uint(bh.w);
                uint32_t bl00 = __float_as_uint(bl.x), bl01 = __float_as_uint(bl.y);
                uint32_t bl10 = __float_as_uint(bl.z), bl11 = __float_as_uint(bl.w);
                MMA_BF16(ca, ahi[kt], bh00, bh01);
                MMA_BF16(cb, ahi[kt], bh10, bh11);
                MMA_BF16(ca, alo[kt], bh00, bh01);
                MMA_BF16(cb, alo[kt], bh10, bh11);
                MMA_BF16(ca, ahi[kt], bl00, bl01);
                MMA_BF16(cb, ahi[kt], bl10, bl11);
            }

            // epilogue: square, per-(row,gen) max over 16 cols, normalize
            float xa0 = ca[0] * ca[0];
            float xa1 = ca[1] * ca[1];
            float xa2 = cb[0] * cb[0];
            float xa3 = cb[1] * cb[1];
            float xb0 = ca[2] * ca[2];
            float xb1 = ca[3] * ca[3];
            float xb2 = cb[2] * cb[2];
            float xb3 = cb[3] * cb[3];

            float ma = fmaxf(fmaxf(xa0, xa1), fmaxf(xa2, xa3));
            float mb = fmaxf(fmaxf(xb0, xb1), fmaxf(xb2, xb3));
            ma = fmaxf(ma, __shfl_xor_sync(0xffffffffu, ma, 1));
            mb = fmaxf(mb, __shfl_xor_sync(0xffffffffu, mb, 1));
            ma = fmaxf(ma, __shfl_xor_sync(0xffffffffu, ma, 2));
            mb = fmaxf(mb, __shfl_xor_sync(0xffffffffu, mb, 2));
            float ia = __fdividef(1.0f, ma);
            float ib = __fdividef(1.0f, mb);

            float* oa = out + ((size_t)g * NPIX + rowA) * KEEPN;
            float* ob = out + ((size_t)g * NPIX + rowB) * KEEPN;
            *reinterpret_cast<float2*>(oa + colq)     = make_float2(xa0 * ia, xa1 * ia);
            *reinterpret_cast<float2*>(oa + colq + 8) = make_float2(xa2 * ia, xa3 * ia);
            *reinterpret_cast<float2*>(ob + colq)     = make_float2(xb0 * ib, xb1 * ib);
            *reinterpret_cast<float2*>(ob + colq + 8) = make_float2(xb2 * ib, xb3 * ib);
        }
    }
}

// ---------------------------------------------------------------------------
extern "C" void kernel_launch(void* const* d_in, const int* in_sizes, int n_in,
                              void* d_out, int out_size)
{
    const float* x  = (const float*)d_in[0];   // [256,256,5]
    const float* qp = (const float*)d_in[1];   // [4,30]
    float* out = (float*)d_out;                // [4,512,512,16]

    const int smem_bytes = (2048 + 8 * 32 * TSTRIDE) * sizeof(float); // 45056
    cudaFuncSetAttribute(qsrgan_mma_kernel,
                         cudaFuncAttributeMaxDynamicSharedMemorySize, smem_bytes);

    precompute_W_kernel<<<1, 128>>>(qp);
    qsrgan_mma_kernel<<<NPIX / 256, 256, smem_bytes>>>(x, out);
}

// round 11
// speedup vs baseline: 3.0515x; 1.0193x over previous
#include <cuda_runtime.h>
#include <cuda_bf16.h>
#include <cstdint>

// QSRGAN: x [256,256,5] f32, q_params [4,30] f32 -> out [4,512,512,16] f32.
//
// Two kernels, bf16 3-term-split MMA (m16n8k16):
//  Kernel 1 (runs once): evolve 32 basis columns through the 6-layer RY+CZ
//    circuit per generator; emit W rows 0..15 as bf16 hi/lo mma B-fragments.
//  Kernel 2: copy fragments to smem (8KB); per pixel bilinear upsample + poly
//    sincos; stage the rank-1 product state TRANSPOSED (S^T[k][pixel], stride
//    36 -> conflict-free stores AND fragment reads). Build BOTH m16 tiles' A
//    hi/lo fragments up front (32 regs), then loop generators: each B hi/lo
//    fragment pair is loaded from smem exactly ONCE (16 LDS.128/thread vs 32
//    in R10 -> -25% L1 wavefronts). mma.sync.m16n8k16 bf16, 3-term split
//    AhiBhi + AloBhi + AhiBlo (residual ~2^-17).
//    Epilogue per (g,m): square, quad-shuffle max, normalize, store.
//  (sum-normalization cancels: p/sum/max(p/sum) = p/max(p))
//
// B fragment layout (bf16 units): for g(0..3), kt(0..1), lane(0..31):
//   float4 index (g*2+kt)*32 + lane holds {nt0_b0, nt0_b1, nt1_b0, nt1_b1}
//   (each element a packed bf16x2); hi array = first 256 float4, lo = next.

#define DIM 32
#define KEEPN 16
#define NGEN 4
#define IW 256
#define NPIX (512*512)
#define TSTRIDE 36     // S^T row stride (floats): conflict-free

__device__ __align__(16) __nv_bfloat16 g_Bfrag[4096];   // hi[2048], lo[2048]

// sin/cos of t in [0, 0.5] via Taylor (err < 1e-9)
__device__ __forceinline__ void poly_sincos(float t, float& s, float& c) {
    float t2 = t * t;
    s = t * (1.0f + t2 * (-1.0f / 6.0f + t2 * (1.0f / 120.0f)));
    c = 1.0f + t2 * (-0.5f + t2 * (1.0f / 24.0f + t2 * (-1.0f / 720.0f)));
}

// pack two floats into bf16x2: lower half = even-k element
__device__ __forceinline__ uint32_t pack_bf16x2(float even, float odd) {
    uint32_t d;
    asm("cvt.rn.bf16x2.f32 %0, %1, %2;" : "=r"(d) : "f"(odd), "f"(even));
    return d;
}

#define MMA_BF16(C, A, B0, B1)                                                 \
    asm volatile("mma.sync.aligned.m16n8k16.row.col.f32.bf16.bf16.f32 "        \
                 "{%0,%1,%2,%3}, {%4,%5,%6,%7}, {%8,%9}, {%0,%1,%2,%3};"       \
                 : "+f"((C)[0]), "+f"((C)[1]), "+f"((C)[2]), "+f"((C)[3])      \
                 : "r"((A)[0]), "r"((A)[1]), "r"((A)[2]), "r"((A)[3]),         \
                   "r"(B0), "r"(B1))

// ---------------------------------------------------------------------------
// Kernel 1: precompute circuit matrix fragments (1 block x 128 threads)
// ---------------------------------------------------------------------------
__global__ void precompute_W_kernel(const float* __restrict__ qp)
{
    const int g = threadIdx.x >> 5;    // generator
    const int j = threadIdx.x & 31;    // basis column (= GEMM k index)

    float st[DIM];
#pragma unroll
    for (int i = 0; i < DIM; i++) st[i] = (i == j) ? 1.0f : 0.0f;

#pragma unroll 1
    for (int d = 0; d < 6; d++) {
#pragma unroll
        for (int q = 0; q < 5; q++) {
            float th = 0.5f * qp[g * 30 + d * 5 + q];
            float s, c;
            sincosf(th, &s, &c);
            const int r = 1 << (4 - q);
#pragma unroll
            for (int i = 0; i < DIM; i++) {
                if ((i & r) == 0) {
                    float a0 = st[i];
                    float a1 = st[i | r];
                    st[i]     = c * a0 - s * a1;
                    st[i | r] = s * a0 + c * a1;
                }
            }
        }
#pragma unroll
        for (int i = 0; i < DIM; i++) {
            if (__popc(i & (i >> 1)) & 1) st[i] = -st[i];
        }
    }

    // Emit fragments. B[k=j][n=g*16+i] = st[i].
    const int kt  = j >> 4;
    const int kk  = j & 15;
    const int r8  = kk >> 3;
    const int c   = (kk >> 1) & 3;
    const int par = kk & 1;
#pragma unroll
    for (int i = 0; i < KEEPN; i++) {
        float v = st[i];
        __nv_bfloat16 hi = __float2bfloat16(v);
        __nv_bfloat16 lo = __float2bfloat16(v - __bfloat162float(hi));
        int lane = 4 * (i & 7) + c;
        int elem = (i >> 3) * 2 + r8;
        int idx  = (((g * 2 + kt) * 32 + lane) * 4 + elem) * 2 + par;
        g_Bfrag[idx]        = hi;
        g_Bfrag[2048 + idx] = lo;
    }
}

// ---------------------------------------------------------------------------
// Kernel 2: main kernel. 1024 blocks x 256 threads, each warp = 32 pixels.
// ---------------------------------------------------------------------------
__global__ void __launch_bounds__(256, 3) qsrgan_mma_kernel(
    const float* __restrict__ x, float* __restrict__ out)
{
    extern __shared__ float smem[];
    float* shB = smem;                 // 2048 floats = 4096 bf16 (hi then lo)
    float* shS = smem + 2048;          // S^T per warp: 32 k-rows x stride 36

    const int tid  = threadIdx.x;
    const int lane = tid & 31;
    const int warp = tid >> 5;

    // cooperative copy of B fragments (8 KB = 512 float4)
    {
        const float4* src = reinterpret_cast<const float4*>(g_Bfrag);
        float4* dst = reinterpret_cast<float4*>(shB);
        dst[tid]       = src[tid];
        dst[tid + 256] = src[tid + 256];
    }

    // ---------------- Phase B: per-pixel state ----------------
    const int p  = blockIdx.x * 256 + tid;
    const int oy = p >> 9;
    const int ox = p & 511;

    float syf = oy * 0.5f - 0.25f;
    int   y0  = __float2int_rd(syf);
    float fy  = syf - (float)y0;
    int y0c = max(y0, 0);
    int y1c = min(y0 + 1, IW - 1);

    float sxf = ox * 0.5f - 0.25f;
    int   x0  = __float2int_rd(sxf);
    float fx  = sxf - (float)x0;
    int x0c = max(x0, 0);
    int x1c = min(x0 + 1, IW - 1);

    const float* p00 = x + (y0c * IW + x0c) * 5;
    const float* p01 = x + (y0c * IW + x1c) * 5;
    const float* p10 = x + (y1c * IW + x0c) * 5;
    const float* p11 = x + (y1c * IW + x1c) * 5;

    float cc[5], ss[5];
#pragma unroll
    for (int c = 0; c < 5; c++) {
        float v00 = __ldg(p00 + c);
        float v01 = __ldg(p01 + c);
        float v10 = __ldg(p10 + c);
        float v11 = __ldg(p11 + c);
        float top = v00 + fx * (v01 - v00);
        float bot = v10 + fx * (v11 - v10);
        float a   = top + fy * (bot - top);
        poly_sincos(0.5f * a, ss[c], cc[c]);     // a in [0,1) -> t in [0,0.5]
    }

    {
        // build t0123[16]; stream 32 amplitudes TRANSPOSED: S^T[k][lane]
        float t01[4];
#pragma unroll
        for (int i = 0; i < 4; i++)
            t01[i] = ((i >> 1) ? ss[0] : cc[0]) * ((i & 1) ? ss[1] : cc[1]);
        float t012[8];
#pragma unroll
        for (int i = 0; i < 8; i++)
            t012[i] = t01[i >> 1] * ((i & 1) ? ss[2] : cc[2]);
        float t0123[16];
#pragma unroll
        for (int i = 0; i < 16; i++)
            t0123[i] = t012[i >> 1] * ((i & 1) ? ss[3] : cc[3]);

        float* Sw = shS + warp * (32 * TSTRIDE) + lane;
        float c4 = cc[4], s4 = ss[4];
#pragma unroll
        for (int i = 0; i < 16; i++) {
            Sw[(2 * i)     * TSTRIDE] = t0123[i] * c4;   // k even
            Sw[(2 * i + 1) * TSTRIDE] = t0123[i] * s4;   // k odd
        }
    }
    __syncthreads();   // B fragments + all states visible

    // ---------------- Phase C: MMA + epilogue ----------------
    const float* Sw = shS + warp * (32 * TSTRIDE);
    const float4* Bhi4 = reinterpret_cast<const float4*>(shB);
    const float4* Blo4 = Bhi4 + 256;
    const int warpBase = blockIdx.x * 256 + warp * 32;
    const int colq = 2 * (lane & 3);

    // A fragments for BOTH m-tiles (bf16 hi/lo): [m][kt][reg] = 32 regs
    uint32_t ahi[2][2][4], alo[2][2][4];
    {
        const int c0 = lane & 3;
#pragma unroll
        for (int m = 0; m < 2; m++) {
            const int r0 = m * 16 + (lane >> 2);
#pragma unroll
            for (int kt = 0; kt < 2; kt++) {
                const int kb = kt * 16 + 2 * c0;
#pragma unroll
                for (int rg = 0; rg < 4; rg++) {
                    int row = r0 + (rg & 1) * 8;
                    int kof = kb + (rg >> 1) * 8;
                    float fe = Sw[kof * TSTRIDE + row];
                    float fo = Sw[(kof + 1) * TSTRIDE + row];
                    uint32_t h = pack_bf16x2(fe, fo);
                    float he = __uint_as_float(h << 16);
                    float ho = __uint_as_float(h & 0xffff0000u);
                    ahi[m][kt][rg] = h;
                    alo[m][kt][rg] = pack_bf16x2(fe - he, fo - ho);
                }
            }
        }
    }

#pragma unroll 1
    for (int g = 0; g < NGEN; g++) {
        float c[2][2][4];   // [m][ntile][reg]
#pragma unroll
        for (int m = 0; m < 2; m++)
#pragma unroll
            for (int nt = 0; nt < 2; nt++)
#pragma unroll
                for (int q = 0; q < 4; q++) c[m][nt][q] = 0.0f;

#pragma unroll
        for (int kt = 0; kt < 2; kt++) {
            const int bidx = (g * 2 + kt) * 32 + lane;
            float4 bh = Bhi4[bidx];   // {nt0_b0, nt0_b1, nt1_b0, nt1_b1}
            float4 bl = Blo4[bidx];
            uint32_t bh00 = __float_as_uint(bh.x), bh01 = __float_as_uint(bh.y);
            uint32_t bh10 = __float_as_uint(bh.z), bh11 = __float_as_uint(bh.w);
            uint32_t bl00 = __float_as_uint(bl.x), bl01 = __float_as_uint(bl.y);
            uint32_t bl10 = __float_as_uint(bl.z), bl11 = __float_as_uint(bl.w);
#pragma unroll
            for (int m = 0; m < 2; m++) {
                MMA_BF16(c[m][0], ahi[m][kt], bh00, bh01);
                MMA_BF16(c[m][1], ahi[m][kt], bh10, bh11);
                MMA_BF16(c[m][0], alo[m][kt], bh00, bh01);
                MMA_BF16(c[m][1], alo[m][kt], bh10, bh11);
                MMA_BF16(c[m][0], ahi[m][kt], bl00, bl01);
                MMA_BF16(c[m][1], ahi[m][kt], bl10, bl11);
            }
        }

        // epilogue per m-tile: square, per-(row,gen) max, normalize, store
#pragma unroll
        for (int m = 0; m < 2; m++) {
            const int rowA = warpBase + m * 16 + (lane >> 2);
            const int rowB = rowA + 8;

            float xa0 = c[m][0][0] * c[m][0][0];
            float xa1 = c[m][0][1] * c[m][0][1];
            float xa2 = c[m][1][0] * c[m][1][0];
            float xa3 = c[m][1][1] * c[m][1][1];
            float xb0 = c[m][0][2] * c[m][0][2];
            float xb1 = c[m][0][3] * c[m][0][3];
            float xb2 = c[m][1][2] * c[m][1][2];
            float xb3 = c[m][1][3] * c[m][1][3];

            float ma = fmaxf(fmaxf(xa0, xa1), fmaxf(xa2, xa3));
            float mb = fmaxf(fmaxf(xb0, xb1), fmaxf(xb2, xb3));
            ma = fmaxf(ma, __shfl_xor_sync(0xffffffffu, ma, 1));
            mb = fmaxf(mb, __shfl_xor_sync(0xffffffffu, mb, 1));
            ma = fmaxf(ma, __shfl_xor_sync(0xffffffffu, ma, 2));
            mb = fmaxf(mb, __shfl_xor_sync(0xffffffffu, mb, 2));
            float ia = __fdividef(1.0f, ma);
            float ib = __fdividef(1.0f, mb);

            float* oa = out + ((size_t)g * NPIX + rowA) * KEEPN;
            float* ob = out + ((size_t)g * NPIX + rowB) * KEEPN;
            *reinterpret_cast<float2*>(oa + colq)     = make_float2(xa0 * ia, xa1 * ia);
            *reinterpret_cast<float2*>(oa + colq + 8) = make_float2(xa2 * ia, xa3 * ia);
            *reinterpret_cast<float2*>(ob + colq)     = make_float2(xb0 * ib, xb1 * ib);
            *reinterpret_cast<float2*>(ob + colq + 8) = make_float2(xb2 * ib, xb3 * ib);
        }
    }
}

// ---------------------------------------------------------------------------
extern "C" void kernel_launch(void* const* d_in, const int* in_sizes, int n_in,
                              void* d_out, int out_size)
{
    const float* x  = (const float*)d_in[0];   // [256,256,5]
    const float* qp = (const float*)d_in[1];   // [4,30]
    float* out = (float*)d_out;                // [4,512,512,16]

    const int smem_bytes = (2048 + 8 * 32 * TSTRIDE) * sizeof(float); // 45056
    cudaFuncSetAttribute(qsrgan_mma_kernel,
                         cudaFuncAttributeMaxDynamicSharedMemorySize, smem_bytes);

    precompute_W_kernel<<<1, 128>>>(qp);
    qsrgan_mma_kernel<<<NPIX / 256, 256, smem_bytes>>>(x, out);
}